// round 15
// baseline (speedup 1.0000x reference)
#include <cuda_runtime.h>
#include <mma.h>

using namespace nvcuda;

#define NN 40000
#define NE 640000
#define D  128
#define NL 4

// ---------------- scratch (device globals; no allocation allowed) ----------
__device__ float g_h[NN * D];
__device__ float g_Ah[NN * D];
__device__ float g_Bh[NN * D];
__device__ float g_Dh[NN * D];
__device__ float g_Eh[NN * D];
__device__ float g_num[NN * D];
__device__ float g_den[NN * D];
__device__ float g_hpre[NN * D];
__device__ float g_e[NE * D];
__device__ float g_etmp[NE * D];
__device__ float g_stats[4 * D];   // [h_sum, h_sumsq, e_sum, e_sumsq]
__device__ float g_bn[4 * D];      // [h_mu, h_rstd, e_mu, e_rstd]

__device__ __forceinline__ void red_add_v4(float* p, float a, float b, float c, float d)
{
    asm volatile("red.global.add.v4.f32 [%0], {%1, %2, %3, %4};"
                 :: "l"(p), "f"(a), "f"(b), "f"(c), "f"(d) : "memory");
}

__device__ __forceinline__ float to_tf32(float x)
{
    float r;
    asm("cvt.rna.tf32.f32 %0, %1;" : "=f"(r) : "f"(x));
    return r;
}

__device__ __forceinline__ void cp_async16(void* smem_dst, const void* gsrc)
{
    unsigned s = (unsigned)__cvta_generic_to_shared(smem_dst);
    asm volatile("cp.async.cg.shared.global [%0], [%1], 16;" :: "r"(s), "l"(gsrc));
}
#define CP_COMMIT() asm volatile("cp.async.commit_group;" ::: "memory")
#define CP_WAIT0()  asm volatile("cp.async.wait_group 0;" ::: "memory")

// ---------------- node GEMM (tf32 WMMA, BM=128, row-guarded) -----------------
#define NAS_STRIDE 36
#define NBS_STRIDE 132
#define NCS_STRIDE 132
#define NAS_FLOATS (128 * NAS_STRIDE)
#define NBS_FLOATS (32 * NBS_STRIDE)
#define NCS_FLOATS (128 * NCS_STRIDE)
#define NAB_FLOATS (NAS_FLOATS + NBS_FLOATS)
#define NODE_SMEM_FLOATS (NAB_FLOATS > NCS_FLOATS ? NAB_FLOATS : NCS_FLOATS)
#define NODE_SMEM_BYTES (NODE_SMEM_FLOATS * 4)
#define NODE_GRID ((NN + 127) / 128)

__global__ __launch_bounds__(256)
void node_gemm_kernel(const float* __restrict__ X, const float* __restrict__ Wl,
                      const float* __restrict__ bl, int zbase)
{
    extern __shared__ float sm[];
    float* As = sm;                  // [128][36] (m,k)
    float* Bs = sm + NAS_FLOATS;     // [32][132] (k,n)
    float* Cs = sm;                  // [128][132] aliases As/Bs

    int z = blockIdx.z + zbase;          // 0:A 1:B 2:D 3:E
    int widx = (z < 2) ? z : z + 1;      // W indices {0,1,3,4}
    const float* W    = Wl + widx * D * D;
    const float* bias = bl + widx * D;
    float* C;
    switch (z) { case 0: C = g_Ah; break; case 1: C = g_Bh; break;
                 case 2: C = g_Dh; break; default: C = g_Eh; break; }

    int tid = threadIdx.x;
    int warp = tid >> 5;
    int wm = warp >> 1;
    int wn = warp & 1;
    int row0 = blockIdx.x * 128;

    wmma::fragment<wmma::accumulator, 16, 16, 8, float> cfrag[2][4];
#pragma unroll
    for (int i = 0; i < 2; i++)
#pragma unroll
        for (int j = 0; j < 4; j++) wmma::fill_fragment(cfrag[i][j], 0.f);

    for (int kc = 0; kc < D; kc += 32) {
#pragma unroll
        for (int p = 0; p < 4; p++) {
            int s = tid + 256 * p;
            int m = s >> 3, c4 = (s & 7) << 2;
            int r = row0 + m;
            float4 v = (r < NN) ? *(const float4*)(X + (size_t)r * D + kc + c4)
                                : make_float4(0.f, 0.f, 0.f, 0.f);
            float* a = As + m * NAS_STRIDE + c4;
            a[0] = to_tf32(v.x); a[1] = to_tf32(v.y);
            a[2] = to_tf32(v.z); a[3] = to_tf32(v.w);
        }
#pragma unroll
        for (int p = 0; p < 4; p++) {
            int s = tid + 256 * p;
            int k = s >> 5, c4 = (s & 31) << 2;
            float4 v = *(const float4*)(W + (kc + k) * D + c4);
            float* bptr = Bs + k * NBS_STRIDE + c4;
            bptr[0] = to_tf32(v.x); bptr[1] = to_tf32(v.y);
            bptr[2] = to_tf32(v.z); bptr[3] = to_tf32(v.w);
        }
        __syncthreads();
#pragma unroll
        for (int ks = 0; ks < 4; ks++) {
            wmma::fragment<wmma::matrix_a, 16, 16, 8, wmma::precision::tf32, wmma::row_major> af[2];
            wmma::fragment<wmma::matrix_b, 16, 16, 8, wmma::precision::tf32, wmma::row_major> bf[4];
#pragma unroll
            for (int i = 0; i < 2; i++)
                wmma::load_matrix_sync(af[i], As + (wm * 32 + i * 16) * NAS_STRIDE + ks * 8, NAS_STRIDE);
#pragma unroll
            for (int j = 0; j < 4; j++)
                wmma::load_matrix_sync(bf[j], Bs + ks * 8 * NBS_STRIDE + wn * 64 + j * 16, NBS_STRIDE);
#pragma unroll
            for (int i = 0; i < 2; i++)
#pragma unroll
                for (int j = 0; j < 4; j++)
                    wmma::mma_sync(cfrag[i][j], af[i], bf[j], cfrag[i][j]);
        }
        __syncthreads();
    }

#pragma unroll
    for (int i = 0; i < 2; i++)
#pragma unroll
        for (int j = 0; j < 4; j++)
            wmma::store_matrix_sync(Cs + (wm * 32 + i * 16) * NCS_STRIDE + wn * 64 + j * 16,
                                    cfrag[i][j], NCS_STRIDE, wmma::mem_row_major);
    __syncthreads();

    int tx = tid & 15, ty = tid >> 4;
    float4 bi0 = *(const float4*)(bias + tx * 8);
    float4 bi1 = *(const float4*)(bias + tx * 8 + 4);
#pragma unroll
    for (int i = 0; i < 8; i++) {
        int rl = ty * 8 + i;
        int r  = row0 + rl;
        if (r >= NN) break;
        const float* crow = Cs + rl * NCS_STRIDE + tx * 8;
        float4 o0 = make_float4(crow[0] + bi0.x, crow[1] + bi0.y,
                                crow[2] + bi0.z, crow[3] + bi0.w);
        float4 o1 = make_float4(crow[4] + bi1.x, crow[5] + bi1.y,
                                crow[6] + bi1.z, crow[7] + bi1.w);
        *(float4*)(C + (size_t)r * D + tx * 8)     = o0;
        *(float4*)(C + (size_t)r * D + tx * 8 + 4) = o1;
    }
}

// ---------------- fused edge kernel (tf32 WMMA, BM=128, cp.async x2-buf) -----
// tf32 inputs come via cp.async (truncation instead of rna rounding).
#define AS_STRIDE 36
#define BS_STRIDE 132
#define CS_STRIDE 132
#define AS_FLOATS (128 * AS_STRIDE)
#define BS_FLOATS (32 * BS_STRIDE)
#define CS_FLOATS (128 * CS_STRIDE)
#define AB_FLOATS (AS_FLOATS + BS_FLOATS)
#define EDGE_SMEM_FLOATS ((2 * AB_FLOATS) > CS_FLOATS ? (2 * AB_FLOATS) : CS_FLOATS)
#define EDGE_SMEM_BYTES (EDGE_SMEM_FLOATS * 4)

__global__ __launch_bounds__(256)
void edge_gemm_fused(const float* __restrict__ Xe, const float* __restrict__ W,
                     const float* __restrict__ bias,
                     const int* __restrict__ src, const int* __restrict__ dst,
                     int do_agg)
{
    extern __shared__ float sm[];
    // double buffers: [A0 B0][A1 B1]; C staging aliases the whole region
    float* Cs = sm;
    __shared__ float s_sum[D], s_sq[D];

    int tid = threadIdx.x;
    if (tid < D) { s_sum[tid] = 0.f; s_sq[tid] = 0.f; }
    int warp = tid >> 5;
    int wm = warp >> 1;
    int wn = warp & 1;
    int row0 = blockIdx.x * 128;

    wmma::fragment<wmma::accumulator, 16, 16, 8, float> cfrag[2][4];
#pragma unroll
    for (int i = 0; i < 2; i++)
#pragma unroll
        for (int j = 0; j < 4; j++) wmma::fill_fragment(cfrag[i][j], 0.f);

    // async tile loaders (raw fp32; MMA truncates to tf32)
    auto load_tiles = [&](int kc, int buf) {
        float* Ab = sm + buf * AB_FLOATS;
        float* Bb = Ab + AS_FLOATS;
#pragma unroll
        for (int p = 0; p < 4; p++) {
            int s = tid + 256 * p;
            int m = s >> 3, c4 = (s & 7) << 2;
            cp_async16(Ab + m * AS_STRIDE + c4, Xe + (size_t)(row0 + m) * D + kc + c4);
        }
#pragma unroll
        for (int p = 0; p < 4; p++) {
            int s = tid + 256 * p;
            int k = s >> 5, c4 = (s & 31) << 2;
            cp_async16(Bb + k * BS_STRIDE + c4, W + (kc + k) * D + c4);
        }
        CP_COMMIT();
    };

    load_tiles(0, 0);
    CP_WAIT0();
    __syncthreads();

#pragma unroll
    for (int kc = 0; kc < 4; kc++) {
        int cur = kc & 1;
        if (kc < 3) load_tiles((kc + 1) * 32, cur ^ 1);

        const float* Ab = sm + cur * AB_FLOATS;
        const float* Bb = Ab + AS_FLOATS;
#pragma unroll
        for (int ks = 0; ks < 4; ks++) {
            wmma::fragment<wmma::matrix_a, 16, 16, 8, wmma::precision::tf32, wmma::row_major> af[2];
            wmma::fragment<wmma::matrix_b, 16, 16, 8, wmma::precision::tf32, wmma::row_major> bf[4];
#pragma unroll
            for (int i = 0; i < 2; i++)
                wmma::load_matrix_sync(af[i], Ab + (wm * 32 + i * 16) * AS_STRIDE + ks * 8, AS_STRIDE);
#pragma unroll
            for (int j = 0; j < 4; j++)
                wmma::load_matrix_sync(bf[j], Bb + ks * 8 * BS_STRIDE + wn * 64 + j * 16, BS_STRIDE);
#pragma unroll
            for (int i = 0; i < 2; i++)
#pragma unroll
                for (int j = 0; j < 4; j++)
                    wmma::mma_sync(cfrag[i][j], af[i], bf[j], cfrag[i][j]);
        }
        if (kc < 3) {
            CP_WAIT0();
            __syncthreads();
        }
    }
    __syncthreads();   // all warps done with As/Bs before C-staging overwrites

#pragma unroll
    for (int i = 0; i < 2; i++)
#pragma unroll
        for (int j = 0; j < 4; j++)
            wmma::store_matrix_sync(Cs + (wm * 32 + i * 16) * CS_STRIDE + wn * 64 + j * 16,
                                    cfrag[i][j], CS_STRIDE, wmma::mem_row_major);
    __syncthreads();

    int tx = tid & 15, ty = tid >> 4;
    float4 bi0 = *(const float4*)(bias + tx * 8);
    float4 bi1 = *(const float4*)(bias + tx * 8 + 4);
    float lsum[8], lsq[8];
#pragma unroll
    for (int j = 0; j < 8; j++) { lsum[j] = 0.f; lsq[j] = 0.f; }

#pragma unroll
    for (int i = 0; i < 8; i++) {
        int rl = ty * 8 + i;
        int r  = row0 + rl;
        const float* crow = Cs + rl * CS_STRIDE + tx * 8;
        int sN = src[r], dN = dst[r];
        const float4* dh = (const float4*)(g_Dh + (size_t)sN * D + tx * 8);
        const float4* eh = (const float4*)(g_Eh + (size_t)dN * D + tx * 8);
        float4 d0 = dh[0], d1 = dh[1];
        float4 e0 = eh[0], e1 = eh[1];
        float v[8];
        v[0] = crow[0] + bi0.x + d0.x + e0.x;
        v[1] = crow[1] + bi0.y + d0.y + e0.y;
        v[2] = crow[2] + bi0.z + d0.z + e0.z;
        v[3] = crow[3] + bi0.w + d0.w + e0.w;
        v[4] = crow[4] + bi1.x + d1.x + e1.x;
        v[5] = crow[5] + bi1.y + d1.y + e1.y;
        v[6] = crow[6] + bi1.z + d1.z + e1.z;
        v[7] = crow[7] + bi1.w + d1.w + e1.w;
        *(float4*)(g_etmp + (size_t)r * D + tx * 8)     = make_float4(v[0], v[1], v[2], v[3]);
        *(float4*)(g_etmp + (size_t)r * D + tx * 8 + 4) = make_float4(v[4], v[5], v[6], v[7]);
#pragma unroll
        for (int j = 0; j < 8; j++) { lsum[j] += v[j]; lsq[j] += v[j] * v[j]; }
        if (do_agg) {
            const float4* bh = (const float4*)(g_Bh + (size_t)sN * D + tx * 8);
            float4 b0v = bh[0], b1v = bh[1];
            float bb[8] = {b0v.x, b0v.y, b0v.z, b0v.w, b1v.x, b1v.y, b1v.z, b1v.w};
            float sig[8];
#pragma unroll
            for (int j = 0; j < 8; j++) sig[j] = 1.f / (1.f + __expf(-v[j]));
            float* np = g_num + (size_t)dN * D + tx * 8;
            float* dp = g_den + (size_t)dN * D + tx * 8;
            red_add_v4(np,     sig[0] * bb[0], sig[1] * bb[1], sig[2] * bb[2], sig[3] * bb[3]);
            red_add_v4(np + 4, sig[4] * bb[4], sig[5] * bb[5], sig[6] * bb[6], sig[7] * bb[7]);
            red_add_v4(dp,     sig[0], sig[1], sig[2], sig[3]);
            red_add_v4(dp + 4, sig[4], sig[5], sig[6], sig[7]);
        }
    }

#pragma unroll
    for (int j = 0; j < 8; j++) {
        atomicAdd(&s_sum[tx * 8 + j], lsum[j]);
        atomicAdd(&s_sq[tx * 8 + j],  lsq[j]);
    }
    __syncthreads();
    if (tid < D) {
        atomicAdd(&g_stats[2 * D + tid], s_sum[tid]);
        atomicAdd(&g_stats[3 * D + tid], s_sq[tid]);
    }
}

// ---------------- h_pre = Ah + num/(den+eps), + BN stats ---------------------
__global__ __launch_bounds__(256)
void hpre_kernel()
{
    __shared__ float ss[256], sq[256];
    int tid  = threadIdx.x;
    int col  = tid & 127;
    int half = tid >> 7;
    int row0 = blockIdx.x * 64;
    float ls = 0.f, lq = 0.f;
    for (int r = row0 + half; r < row0 + 64; r += 2) {
        int idx = r * D + col;
        float v = g_Ah[idx] + g_num[idx] / (g_den[idx] + 1e-6f);
        g_hpre[idx] = v;
        ls += v; lq += v * v;
    }
    ss[tid] = ls; sq[tid] = lq;
    __syncthreads();
    if (tid < 128) {
        atomicAdd(&g_stats[tid],     ss[tid] + ss[tid + 128]);
        atomicAdd(&g_stats[D + tid], sq[tid] + sq[tid + 128]);
    }
}

// ---------------- finalize BN statistics -------------------------------------
__global__ void finalize_stats_kernel()
{
    int c = threadIdx.x;
    float inN = 1.f / (float)NN, inE = 1.f / (float)NE;
    float hmu  = g_stats[c] * inN;
    float hvar = g_stats[D + c] * inN - hmu * hmu;
    g_bn[c]     = hmu;
    g_bn[D + c] = rsqrtf(fmaxf(hvar, 0.f) + 1e-5f);
    float emu  = g_stats[2 * D + c] * inE;
    float evar = g_stats[3 * D + c] * inE - emu * emu;
    g_bn[2 * D + c] = emu;
    g_bn[3 * D + c] = rsqrtf(fmaxf(evar, 0.f) + 1e-5f);
}

// ---------------- h = h_in + relu(bn(h_pre)) ---------------------------------
__global__ __launch_bounds__(256)
void h_apply_kernel(const float* __restrict__ hin, float* __restrict__ hout,
                    const float* __restrict__ gamma, const float* __restrict__ beta)
{
    int i = blockIdx.x * blockDim.x + threadIdx.x;
    if (i >= NN * D / 4) return;
    int c = (i & 31) << 2;
    float4 p  = ((const float4*)g_hpre)[i];
    float4 x  = ((const float4*)hin)[i];
    float4 mu = *(const float4*)(g_bn + c);
    float4 rs = *(const float4*)(g_bn + D + c);
    float4 ga = *(const float4*)(gamma + c);
    float4 be = *(const float4*)(beta + c);
    float4 o;
    o.x = x.x + fmaxf((p.x - mu.x) * rs.x * ga.x + be.x, 0.f);
    o.y = x.y + fmaxf((p.y - mu.y) * rs.y * ga.y + be.y, 0.f);
    o.z = x.z + fmaxf((p.z - mu.z) * rs.z * ga.z + be.z, 0.f);
    o.w = x.w + fmaxf((p.w - mu.w) * rs.w * ga.w + be.w, 0.f);
    ((float4*)hout)[i] = o;
}

// ---------------- e = e_in + relu(bn(e_tmp)) ----------------------------------
__global__ __launch_bounds__(256)
void e_apply_kernel(const float* __restrict__ ein, float* __restrict__ eout,
                    const float* __restrict__ gamma, const float* __restrict__ beta)
{
    int i = blockIdx.x * blockDim.x + threadIdx.x;
    if (i >= NE * D / 4) return;
    int c = (i & 31) << 2;
    float4 p  = ((const float4*)g_etmp)[i];
    float4 x  = ((const float4*)ein)[i];
    float4 mu = *(const float4*)(g_bn + 2 * D + c);
    float4 rs = *(const float4*)(g_bn + 3 * D + c);
    float4 ga = *(const float4*)(gamma + c);
    float4 be = *(const float4*)(beta + c);
    float4 o;
    o.x = x.x + fmaxf((p.x - mu.x) * rs.x * ga.x + be.x, 0.f);
    o.y = x.y + fmaxf((p.y - mu.y) * rs.y * ga.y + be.y, 0.f);
    o.z = x.z + fmaxf((p.z - mu.z) * rs.z * ga.z + be.z, 0.f);
    o.w = x.w + fmaxf((p.w - mu.w) * rs.w * ga.w + be.w, 0.f);
    ((float4*)eout)[i] = o;
}

// ---------------- launcher ----------------------------------------------------
extern "C" void kernel_launch(void* const* d_in, const int* in_sizes, int n_in,
                              void* d_out, int out_size)
{
    const float* h_in  = (const float*)d_in[0];
    const float* e_in  = (const float*)d_in[1];
    const float* W     = (const float*)d_in[2];
    const float* b     = (const float*)d_in[3];
    const float* gamma = (const float*)d_in[4];
    const float* beta  = (const float*)d_in[5];
    const int*   src   = (const int*)d_in[6];
    const int*   dst   = (const int*)d_in[7];
    float* out = (float*)d_out;

    static int init_done = 0;
    static cudaStream_t s1;
    static cudaEvent_t evFork[NL], evJoin[NL];
    if (!init_done) {
        cudaFuncSetAttribute(edge_gemm_fused,
                             cudaFuncAttributeMaxDynamicSharedMemorySize, EDGE_SMEM_BYTES);
        cudaFuncSetAttribute(node_gemm_kernel,
                             cudaFuncAttributeMaxDynamicSharedMemorySize, NODE_SMEM_BYTES);
        cudaStreamCreateWithFlags(&s1, cudaStreamNonBlocking);
        for (int i = 0; i < NL; i++) {
            cudaEventCreateWithFlags(&evFork[i], cudaEventDisableTiming);
            cudaEventCreateWithFlags(&evJoin[i], cudaEventDisableTiming);
        }
        init_done = 1;
    }

    float *p_num, *p_den, *p_stats, *p_h, *p_e;
    cudaGetSymbolAddress((void**)&p_num,   g_num);
    cudaGetSymbolAddress((void**)&p_den,   g_den);
    cudaGetSymbolAddress((void**)&p_stats, g_stats);
    cudaGetSymbolAddress((void**)&p_h,     g_h);
    cudaGetSymbolAddress((void**)&p_e,     g_e);

    // Output h = h_before (the input h, unchanged by reference semantics)
    cudaMemcpyAsync(out, h_in, (size_t)NN * D * sizeof(float),
                    cudaMemcpyDeviceToDevice, 0);

    for (int l = 0; l < NL; l++) {
        const float* hcur = (l == 0) ? h_in : p_h;
        const float* ecur = (l == 0) ? e_in : p_e;
        const float* Wl = W + (size_t)l * 5 * D * D;
        const float* bl = b + (size_t)l * 5 * D;
        int last = (l == NL - 1);

        cudaMemsetAsync(p_stats, 0, 4 * D * sizeof(float), 0);
        if (!last) {
            cudaMemsetAsync(p_num, 0, (size_t)NN * D * sizeof(float), 0);
            cudaMemsetAsync(p_den, 0, (size_t)NN * D * sizeof(float), 0);
        }

        if (!last)
            node_gemm_kernel<<<dim3(NODE_GRID, 1, 4), 256, NODE_SMEM_BYTES>>>(hcur, Wl, bl, 0);
        else
            node_gemm_kernel<<<dim3(NODE_GRID, 1, 2), 256, NODE_SMEM_BYTES>>>(hcur, Wl, bl, 2);

        // join: previous layer's e_apply (on s1) must have produced p_e
        if (l > 0)
            cudaStreamWaitEvent(0, evJoin[l - 1], 0);

        edge_gemm_fused<<<NE / 128, 256, EDGE_SMEM_BYTES>>>(
            ecur, Wl + 2 * D * D, bl + 2 * D, src, dst, last ? 0 : 1);

        if (!last) hpre_kernel<<<NN / 64, 256>>>();
        finalize_stats_kernel<<<1, D>>>();

        if (!last) {
            // fork: e_apply on s1 overlaps h_apply + next layer's node GEMM
            cudaEventRecord(evFork[l], 0);
            cudaStreamWaitEvent(s1, evFork[l], 0);
            e_apply_kernel<<<(NE * D / 4 + 255) / 256, 256, 0, s1>>>(
                ecur, p_e, gamma + (size_t)(l * 2 + 1) * D, beta + (size_t)(l * 2 + 1) * D);
            cudaEventRecord(evJoin[l], s1);

            h_apply_kernel<<<(NN * D / 4 + 255) / 256, 256>>>(
                hcur, p_h, gamma + (size_t)(l * 2) * D, beta + (size_t)(l * 2) * D);
        } else {
            e_apply_kernel<<<(NE * D / 4 + 255) / 256, 256>>>(
                ecur, out + (size_t)NN * D,
                gamma + (size_t)(l * 2 + 1) * D, beta + (size_t)(l * 2 + 1) * D);
        }
    }
}

// round 16
// speedup vs baseline: 1.3827x; 1.3827x over previous
#include <cuda_runtime.h>
#include <mma.h>

using namespace nvcuda;

#define NN 40000
#define NE 640000
#define D  128
#define NL 4

// ---------------- scratch (device globals; no allocation allowed) ----------
__device__ float g_h[NN * D];
__device__ float g_Ah[NN * D];
__device__ float g_Bh[NN * D];
__device__ float g_Dh[NN * D];
__device__ float g_Eh[NN * D];
__device__ float g_num[NN * D];
__device__ float g_den[NN * D];
__device__ float g_hpre[NN * D];
__device__ float g_e[NE * D];
__device__ float g_etmp[NE * D];
__device__ float g_stats[4 * D];   // [h_sum, h_sumsq, e_sum, e_sumsq]
__device__ float g_bn[4 * D];      // [h_mu, h_rstd, e_mu, e_rstd]

__device__ __forceinline__ void red_add_v4(float* p, float a, float b, float c, float d)
{
    asm volatile("red.global.add.v4.f32 [%0], {%1, %2, %3, %4};"
                 :: "l"(p), "f"(a), "f"(b), "f"(c), "f"(d) : "memory");
}

__device__ __forceinline__ float to_tf32(float x)
{
    float r;
    asm("cvt.rna.tf32.f32 %0, %1;" : "=f"(r) : "f"(x));
    return r;
}

// ---------------- node GEMM (tf32 WMMA, BM=128, row-guarded) -----------------
// z via blockIdx.z + zbase: 0:A 1:B 2:D 3:E
#define NAS_STRIDE 36
#define NBS_STRIDE 132
#define NCS_STRIDE 132
#define NAS_FLOATS (128 * NAS_STRIDE)
#define NBS_FLOATS (32 * NBS_STRIDE)
#define NCS_FLOATS (128 * NCS_STRIDE)
#define NAB_FLOATS (NAS_FLOATS + NBS_FLOATS)
#define NODE_SMEM_FLOATS (NAB_FLOATS > NCS_FLOATS ? NAB_FLOATS : NCS_FLOATS)
#define NODE_SMEM_BYTES (NODE_SMEM_FLOATS * 4)
#define NODE_GRID ((NN + 127) / 128)

__global__ __launch_bounds__(256)
void node_gemm_kernel(const float* __restrict__ X, const float* __restrict__ Wl,
                      const float* __restrict__ bl, int zbase)
{
    extern __shared__ float sm[];
    float* As = sm;                  // [128][36] (m,k)
    float* Bs = sm + NAS_FLOATS;     // [32][132] (k,n)
    float* Cs = sm;                  // [128][132] aliases As/Bs

    int z = blockIdx.z + zbase;          // 0:A 1:B 2:D 3:E
    int widx = (z < 2) ? z : z + 1;      // W indices {0,1,3,4}
    const float* W    = Wl + widx * D * D;
    const float* bias = bl + widx * D;
    float* C;
    switch (z) { case 0: C = g_Ah; break; case 1: C = g_Bh; break;
                 case 2: C = g_Dh; break; default: C = g_Eh; break; }

    int tid = threadIdx.x;
    int warp = tid >> 5;
    int wm = warp >> 1;
    int wn = warp & 1;
    int row0 = blockIdx.x * 128;

    wmma::fragment<wmma::accumulator, 16, 16, 8, float> cfrag[2][4];
#pragma unroll
    for (int i = 0; i < 2; i++)
#pragma unroll
        for (int j = 0; j < 4; j++) wmma::fill_fragment(cfrag[i][j], 0.f);

    for (int kc = 0; kc < D; kc += 32) {
#pragma unroll
        for (int p = 0; p < 4; p++) {
            int s = tid + 256 * p;
            int m = s >> 3, c4 = (s & 7) << 2;
            int r = row0 + m;
            float4 v = (r < NN) ? *(const float4*)(X + (size_t)r * D + kc + c4)
                                : make_float4(0.f, 0.f, 0.f, 0.f);
            float* a = As + m * NAS_STRIDE + c4;
            a[0] = to_tf32(v.x); a[1] = to_tf32(v.y);
            a[2] = to_tf32(v.z); a[3] = to_tf32(v.w);
        }
#pragma unroll
        for (int p = 0; p < 4; p++) {
            int s = tid + 256 * p;
            int k = s >> 5, c4 = (s & 31) << 2;
            float4 v = *(const float4*)(W + (kc + k) * D + c4);
            float* bptr = Bs + k * NBS_STRIDE + c4;
            bptr[0] = to_tf32(v.x); bptr[1] = to_tf32(v.y);
            bptr[2] = to_tf32(v.z); bptr[3] = to_tf32(v.w);
        }
        __syncthreads();
#pragma unroll
        for (int ks = 0; ks < 4; ks++) {
            wmma::fragment<wmma::matrix_a, 16, 16, 8, wmma::precision::tf32, wmma::row_major> af[2];
            wmma::fragment<wmma::matrix_b, 16, 16, 8, wmma::precision::tf32, wmma::row_major> bf[4];
#pragma unroll
            for (int i = 0; i < 2; i++)
                wmma::load_matrix_sync(af[i], As + (wm * 32 + i * 16) * NAS_STRIDE + ks * 8, NAS_STRIDE);
#pragma unroll
            for (int j = 0; j < 4; j++)
                wmma::load_matrix_sync(bf[j], Bs + ks * 8 * NBS_STRIDE + wn * 64 + j * 16, NBS_STRIDE);
#pragma unroll
            for (int i = 0; i < 2; i++)
#pragma unroll
                for (int j = 0; j < 4; j++)
                    wmma::mma_sync(cfrag[i][j], af[i], bf[j], cfrag[i][j]);
        }
        __syncthreads();
    }

#pragma unroll
    for (int i = 0; i < 2; i++)
#pragma unroll
        for (int j = 0; j < 4; j++)
            wmma::store_matrix_sync(Cs + (wm * 32 + i * 16) * NCS_STRIDE + wn * 64 + j * 16,
                                    cfrag[i][j], NCS_STRIDE, wmma::mem_row_major);
    __syncthreads();

    int tx = tid & 15, ty = tid >> 4;
    float4 bi0 = *(const float4*)(bias + tx * 8);
    float4 bi1 = *(const float4*)(bias + tx * 8 + 4);
#pragma unroll
    for (int i = 0; i < 8; i++) {
        int rl = ty * 8 + i;
        int r  = row0 + rl;
        if (r >= NN) break;
        const float* crow = Cs + rl * NCS_STRIDE + tx * 8;
        float4 o0 = make_float4(crow[0] + bi0.x, crow[1] + bi0.y,
                                crow[2] + bi0.z, crow[3] + bi0.w);
        float4 o1 = make_float4(crow[4] + bi1.x, crow[5] + bi1.y,
                                crow[6] + bi1.z, crow[7] + bi1.w);
        *(float4*)(C + (size_t)r * D + tx * 8)     = o0;
        *(float4*)(C + (size_t)r * D + tx * 8 + 4) = o1;
    }
}

// ---------------- fused edge kernel (tf32 WMMA, BM=128) ----------------------
#define AS_STRIDE 36
#define BS_STRIDE 132
#define CS_STRIDE 132
#define AS_FLOATS (128 * AS_STRIDE)
#define BS_FLOATS (32 * BS_STRIDE)
#define CS_FLOATS (128 * CS_STRIDE)
#define AB_FLOATS (AS_FLOATS + BS_FLOATS)
#define EDGE_SMEM_FLOATS (AB_FLOATS > CS_FLOATS ? AB_FLOATS : CS_FLOATS)
#define EDGE_SMEM_BYTES (EDGE_SMEM_FLOATS * 4)

__global__ __launch_bounds__(256)
void edge_gemm_fused(const float* __restrict__ Xe, const float* __restrict__ W,
                     const float* __restrict__ bias,
                     const int* __restrict__ src, const int* __restrict__ dst,
                     int do_agg)
{
    extern __shared__ float sm[];
    float* As = sm;
    float* Bs = sm + AS_FLOATS;
    float* Cs = sm;                         // aliases As/Bs
    __shared__ float s_sum[D], s_sq[D];

    int tid = threadIdx.x;
    if (tid < D) { s_sum[tid] = 0.f; s_sq[tid] = 0.f; }
    int warp = tid >> 5;
    int wm = warp >> 1;
    int wn = warp & 1;
    int row0 = blockIdx.x * 128;

    wmma::fragment<wmma::accumulator, 16, 16, 8, float> cfrag[2][4];
#pragma unroll
    for (int i = 0; i < 2; i++)
#pragma unroll
        for (int j = 0; j < 4; j++) wmma::fill_fragment(cfrag[i][j], 0.f);

    for (int kc = 0; kc < D; kc += 32) {
#pragma unroll
        for (int p = 0; p < 4; p++) {
            int s = tid + 256 * p;
            int m = s >> 3, c4 = (s & 7) << 2;
            float4 v = *(const float4*)(Xe + (size_t)(row0 + m) * D + kc + c4);
            float* a = As + m * AS_STRIDE + c4;
            a[0] = to_tf32(v.x); a[1] = to_tf32(v.y);
            a[2] = to_tf32(v.z); a[3] = to_tf32(v.w);
        }
#pragma unroll
        for (int p = 0; p < 4; p++) {
            int s = tid + 256 * p;
            int k = s >> 5, c4 = (s & 31) << 2;
            float4 v = *(const float4*)(W + (kc + k) * D + c4);
            float* bptr = Bs + k * BS_STRIDE + c4;
            bptr[0] = to_tf32(v.x); bptr[1] = to_tf32(v.y);
            bptr[2] = to_tf32(v.z); bptr[3] = to_tf32(v.w);
        }
        __syncthreads();
#pragma unroll
        for (int ks = 0; ks < 4; ks++) {
            wmma::fragment<wmma::matrix_a, 16, 16, 8, wmma::precision::tf32, wmma::row_major> af[2];
            wmma::fragment<wmma::matrix_b, 16, 16, 8, wmma::precision::tf32, wmma::row_major> bf[4];
#pragma unroll
            for (int i = 0; i < 2; i++)
                wmma::load_matrix_sync(af[i], As + (wm * 32 + i * 16) * AS_STRIDE + ks * 8, AS_STRIDE);
#pragma unroll
            for (int j = 0; j < 4; j++)
                wmma::load_matrix_sync(bf[j], Bs + ks * 8 * BS_STRIDE + wn * 64 + j * 16, BS_STRIDE);
#pragma unroll
            for (int i = 0; i < 2; i++)
#pragma unroll
                for (int j = 0; j < 4; j++)
                    wmma::mma_sync(cfrag[i][j], af[i], bf[j], cfrag[i][j]);
        }
        __syncthreads();
    }

#pragma unroll
    for (int i = 0; i < 2; i++)
#pragma unroll
        for (int j = 0; j < 4; j++)
            wmma::store_matrix_sync(Cs + (wm * 32 + i * 16) * CS_STRIDE + wn * 64 + j * 16,
                                    cfrag[i][j], CS_STRIDE, wmma::mem_row_major);
    __syncthreads();

    int tx = tid & 15, ty = tid >> 4;
    float4 bi0 = *(const float4*)(bias + tx * 8);
    float4 bi1 = *(const float4*)(bias + tx * 8 + 4);
    float lsum[8], lsq[8];
#pragma unroll
    for (int j = 0; j < 8; j++) { lsum[j] = 0.f; lsq[j] = 0.f; }

#pragma unroll
    for (int i = 0; i < 8; i++) {
        int rl = ty * 8 + i;
        int r  = row0 + rl;
        const float* crow = Cs + rl * CS_STRIDE + tx * 8;
        int sN = src[r], dN = dst[r];
        const float4* dh = (const float4*)(g_Dh + (size_t)sN * D + tx * 8);
        const float4* eh = (const float4*)(g_Eh + (size_t)dN * D + tx * 8);
        float4 d0 = dh[0], d1 = dh[1];
        float4 e0 = eh[0], e1 = eh[1];
        float v[8];
        v[0] = crow[0] + bi0.x + d0.x + e0.x;
        v[1] = crow[1] + bi0.y + d0.y + e0.y;
        v[2] = crow[2] + bi0.z + d0.z + e0.z;
        v[3] = crow[3] + bi0.w + d0.w + e0.w;
        v[4] = crow[4] + bi1.x + d1.x + e1.x;
        v[5] = crow[5] + bi1.y + d1.y + e1.y;
        v[6] = crow[6] + bi1.z + d1.z + e1.z;
        v[7] = crow[7] + bi1.w + d1.w + e1.w;
        *(float4*)(g_etmp + (size_t)r * D + tx * 8)     = make_float4(v[0], v[1], v[2], v[3]);
        *(float4*)(g_etmp + (size_t)r * D + tx * 8 + 4) = make_float4(v[4], v[5], v[6], v[7]);
#pragma unroll
        for (int j = 0; j < 8; j++) { lsum[j] += v[j]; lsq[j] += v[j] * v[j]; }
        if (do_agg) {
            const float4* bh = (const float4*)(g_Bh + (size_t)sN * D + tx * 8);
            float4 b0v = bh[0], b1v = bh[1];
            float bb[8] = {b0v.x, b0v.y, b0v.z, b0v.w, b1v.x, b1v.y, b1v.z, b1v.w};
            float sig[8];
#pragma unroll
            for (int j = 0; j < 8; j++) sig[j] = 1.f / (1.f + __expf(-v[j]));
            float* np = g_num + (size_t)dN * D + tx * 8;
            float* dp = g_den + (size_t)dN * D + tx * 8;
            red_add_v4(np,     sig[0] * bb[0], sig[1] * bb[1], sig[2] * bb[2], sig[3] * bb[3]);
            red_add_v4(np + 4, sig[4] * bb[4], sig[5] * bb[5], sig[6] * bb[6], sig[7] * bb[7]);
            red_add_v4(dp,     sig[0], sig[1], sig[2], sig[3]);
            red_add_v4(dp + 4, sig[4], sig[5], sig[6], sig[7]);
        }
    }

#pragma unroll
    for (int j = 0; j < 8; j++) {
        atomicAdd(&s_sum[tx * 8 + j], lsum[j]);
        atomicAdd(&s_sq[tx * 8 + j],  lsq[j]);
    }
    __syncthreads();
    if (tid < D) {
        atomicAdd(&g_stats[2 * D + tid], s_sum[tid]);
        atomicAdd(&g_stats[3 * D + tid], s_sq[tid]);
    }
}

// ---------------- h_pre = Ah + num/(den+eps), + BN stats ---------------------
__global__ __launch_bounds__(256)
void hpre_kernel()
{
    __shared__ float ss[256], sq[256];
    int tid  = threadIdx.x;
    int col  = tid & 127;
    int half = tid >> 7;
    int row0 = blockIdx.x * 64;
    float ls = 0.f, lq = 0.f;
    for (int r = row0 + half; r < row0 + 64; r += 2) {
        int idx = r * D + col;
        float v = g_Ah[idx] + g_num[idx] / (g_den[idx] + 1e-6f);
        g_hpre[idx] = v;
        ls += v; lq += v * v;
    }
    ss[tid] = ls; sq[tid] = lq;
    __syncthreads();
    if (tid < 128) {
        atomicAdd(&g_stats[tid],     ss[tid] + ss[tid + 128]);
        atomicAdd(&g_stats[D + tid], sq[tid] + sq[tid + 128]);
    }
}

// ---------------- finalize BN statistics -------------------------------------
__global__ void finalize_stats_kernel()
{
    int c = threadIdx.x;
    float inN = 1.f / (float)NN, inE = 1.f / (float)NE;
    float hmu  = g_stats[c] * inN;
    float hvar = g_stats[D + c] * inN - hmu * hmu;
    g_bn[c]     = hmu;
    g_bn[D + c] = rsqrtf(fmaxf(hvar, 0.f) + 1e-5f);
    float emu  = g_stats[2 * D + c] * inE;
    float evar = g_stats[3 * D + c] * inE - emu * emu;
    g_bn[2 * D + c] = emu;
    g_bn[3 * D + c] = rsqrtf(fmaxf(evar, 0.f) + 1e-5f);
}

// ---------------- h = h_in + relu(bn(h_pre)) ---------------------------------
__global__ __launch_bounds__(256)
void h_apply_kernel(const float* __restrict__ hin, float* __restrict__ hout,
                    const float* __restrict__ gamma, const float* __restrict__ beta)
{
    int i = blockIdx.x * blockDim.x + threadIdx.x;
    if (i >= NN * D / 4) return;
    int c = (i & 31) << 2;
    float4 p  = ((const float4*)g_hpre)[i];
    float4 x  = ((const float4*)hin)[i];
    float4 mu = *(const float4*)(g_bn + c);
    float4 rs = *(const float4*)(g_bn + D + c);
    float4 ga = *(const float4*)(gamma + c);
    float4 be = *(const float4*)(beta + c);
    float4 o;
    o.x = x.x + fmaxf((p.x - mu.x) * rs.x * ga.x + be.x, 0.f);
    o.y = x.y + fmaxf((p.y - mu.y) * rs.y * ga.y + be.y, 0.f);
    o.z = x.z + fmaxf((p.z - mu.z) * rs.z * ga.z + be.z, 0.f);
    o.w = x.w + fmaxf((p.w - mu.w) * rs.w * ga.w + be.w, 0.f);
    ((float4*)hout)[i] = o;
}

// ---------------- e = e_in + relu(bn(e_tmp)) ----------------------------------
__global__ __launch_bounds__(256)
void e_apply_kernel(const float* __restrict__ ein, float* __restrict__ eout,
                    const float* __restrict__ gamma, const float* __restrict__ beta)
{
    int i = blockIdx.x * blockDim.x + threadIdx.x;
    if (i >= NE * D / 4) return;
    int c = (i & 31) << 2;
    float4 p  = ((const float4*)g_etmp)[i];
    float4 x  = ((const float4*)ein)[i];
    float4 mu = *(const float4*)(g_bn + 2 * D + c);
    float4 rs = *(const float4*)(g_bn + 3 * D + c);
    float4 ga = *(const float4*)(gamma + c);
    float4 be = *(const float4*)(beta + c);
    float4 o;
    o.x = x.x + fmaxf((p.x - mu.x) * rs.x * ga.x + be.x, 0.f);
    o.y = x.y + fmaxf((p.y - mu.y) * rs.y * ga.y + be.y, 0.f);
    o.z = x.z + fmaxf((p.z - mu.z) * rs.z * ga.z + be.z, 0.f);
    o.w = x.w + fmaxf((p.w - mu.w) * rs.w * ga.w + be.w, 0.f);
    ((float4*)eout)[i] = o;
}

// ---------------- launcher ----------------------------------------------------
extern "C" void kernel_launch(void* const* d_in, const int* in_sizes, int n_in,
                              void* d_out, int out_size)
{
    const float* h_in  = (const float*)d_in[0];
    const float* e_in  = (const float*)d_in[1];
    const float* W     = (const float*)d_in[2];
    const float* b     = (const float*)d_in[3];
    const float* gamma = (const float*)d_in[4];
    const float* beta  = (const float*)d_in[5];
    const int*   src   = (const int*)d_in[6];
    const int*   dst   = (const int*)d_in[7];
    float* out = (float*)d_out;

    static int init_done = 0;
    static cudaStream_t s1;
    static cudaEvent_t evFork[NL], evJoin[NL], evAfork[NL], evAh[NL];
    if (!init_done) {
        cudaFuncSetAttribute(edge_gemm_fused,
                             cudaFuncAttributeMaxDynamicSharedMemorySize, EDGE_SMEM_BYTES);
        cudaFuncSetAttribute(node_gemm_kernel,
                             cudaFuncAttributeMaxDynamicSharedMemorySize, NODE_SMEM_BYTES);
        cudaStreamCreateWithFlags(&s1, cudaStreamNonBlocking);
        for (int i = 0; i < NL; i++) {
            cudaEventCreateWithFlags(&evFork[i],  cudaEventDisableTiming);
            cudaEventCreateWithFlags(&evJoin[i],  cudaEventDisableTiming);
            cudaEventCreateWithFlags(&evAfork[i], cudaEventDisableTiming);
            cudaEventCreateWithFlags(&evAh[i],    cudaEventDisableTiming);
        }
        init_done = 1;
    }

    float *p_num, *p_den, *p_stats, *p_h, *p_e;
    cudaGetSymbolAddress((void**)&p_num,   g_num);
    cudaGetSymbolAddress((void**)&p_den,   g_den);
    cudaGetSymbolAddress((void**)&p_stats, g_stats);
    cudaGetSymbolAddress((void**)&p_h,     g_h);
    cudaGetSymbolAddress((void**)&p_e,     g_e);

    // Output h = h_before (the input h, unchanged by reference semantics)
    cudaMemcpyAsync(out, h_in, (size_t)NN * D * sizeof(float),
                    cudaMemcpyDeviceToDevice, 0);

    for (int l = 0; l < NL; l++) {
        const float* hcur = (l == 0) ? h_in : p_h;
        const float* ecur = (l == 0) ? e_in : p_e;
        const float* Wl = W + (size_t)l * 5 * D * D;
        const float* bl = b + (size_t)l * 5 * D;
        int last = (l == NL - 1);

        cudaMemsetAsync(p_stats, 0, 4 * D * sizeof(float), 0);
        if (!last) {
            cudaMemsetAsync(p_num, 0, (size_t)NN * D * sizeof(float), 0);
            cudaMemsetAsync(p_den, 0, (size_t)NN * D * sizeof(float), 0);
        }

        if (!last) {
            // B, D, E on stream 0 (edge kernel needs all three)
            node_gemm_kernel<<<dim3(NODE_GRID, 1, 3), 256, NODE_SMEM_BYTES>>>(hcur, Wl, bl, 1);
            // Ah on s1 — only needed by hpre; hides under the edge kernel
            cudaEventRecord(evAfork[l], 0);
            cudaStreamWaitEvent(s1, evAfork[l], 0);
            node_gemm_kernel<<<dim3(NODE_GRID, 1, 1), 256, NODE_SMEM_BYTES, s1>>>(hcur, Wl, bl, 0);
            cudaEventRecord(evAh[l], s1);
        } else {
            // only Dh, Eh needed for the final edge update
            node_gemm_kernel<<<dim3(NODE_GRID, 1, 2), 256, NODE_SMEM_BYTES>>>(hcur, Wl, bl, 2);
        }

        // join: previous layer's e_apply (on s1) must have produced p_e
        if (l > 0)
            cudaStreamWaitEvent(0, evJoin[l - 1], 0);

        edge_gemm_fused<<<NE / 128, 256, EDGE_SMEM_BYTES>>>(
            ecur, Wl + 2 * D * D, bl + 2 * D, src, dst, last ? 0 : 1);

        if (!last) {
            cudaStreamWaitEvent(0, evAh[l], 0);   // Ah ready before hpre
            hpre_kernel<<<NN / 64, 256>>>();
        }
        finalize_stats_kernel<<<1, D>>>();

        if (!last) {
            // fork: e_apply on s1 overlaps h_apply + next layer's node GEMM
            cudaEventRecord(evFork[l], 0);
            cudaStreamWaitEvent(s1, evFork[l], 0);
            e_apply_kernel<<<(NE * D / 4 + 255) / 256, 256, 0, s1>>>(
                ecur, p_e, gamma + (size_t)(l * 2 + 1) * D, beta + (size_t)(l * 2 + 1) * D);
            cudaEventRecord(evJoin[l], s1);

            h_apply_kernel<<<(NN * D / 4 + 255) / 256, 256>>>(
                hcur, p_h, gamma + (size_t)(l * 2) * D, beta + (size_t)(l * 2) * D);
        } else {
            e_apply_kernel<<<(NE * D / 4 + 255) / 256, 256>>>(
                ecur, out + (size_t)NN * D,
                gamma + (size_t)(l * 2 + 1) * D, beta + (size_t)(l * 2 + 1) * D);
        }
    }
}

// round 17
// speedup vs baseline: 1.3942x; 1.0083x over previous
#include <cuda_runtime.h>
#include <mma.h>

using namespace nvcuda;

#define NN 40000
#define NE 640000
#define D  128
#define NL 4

// ---------------- scratch (device globals; no allocation allowed) ----------
__device__ float g_h[NN * D];
__device__ float g_Ah[NN * D];
__device__ float g_Bh[NN * D];
__device__ float g_Dh[NN * D];
__device__ float g_Eh[NN * D];
__device__ float g_num[NN * D];
__device__ float g_den[NN * D];
__device__ float g_hpre[NN * D];
__device__ float g_e[NE * D];
__device__ float g_etmp[NE * D];
__device__ float g_stats[4 * D];   // [h_sum, h_sumsq, e_sum, e_sumsq]
__device__ float g_bn[4 * D];      // [h_mu, h_rstd, e_mu, e_rstd]

__device__ __forceinline__ void red_add_v4(float* p, float a, float b, float c, float d)
{
    asm volatile("red.global.add.v4.f32 [%0], {%1, %2, %3, %4};"
                 :: "l"(p), "f"(a), "f"(b), "f"(c), "f"(d) : "memory");
}

__device__ __forceinline__ float to_tf32(float x)
{
    float r;
    asm("cvt.rna.tf32.f32 %0, %1;" : "=f"(r) : "f"(x));
    return r;
}

// ---------------- node GEMM (tf32 WMMA, BM=128, row-guarded) -----------------
#define NAS_STRIDE 36
#define NBS_STRIDE 132
#define NCS_STRIDE 132
#define NAS_FLOATS (128 * NAS_STRIDE)
#define NBS_FLOATS (32 * NBS_STRIDE)
#define NCS_FLOATS (128 * NCS_STRIDE)
#define NAB_FLOATS (NAS_FLOATS + NBS_FLOATS)
#define NODE_SMEM_FLOATS (NAB_FLOATS > NCS_FLOATS ? NAB_FLOATS : NCS_FLOATS)
#define NODE_SMEM_BYTES (NODE_SMEM_FLOATS * 4)
#define NODE_GRID ((NN + 127) / 128)

__global__ __launch_bounds__(256)
void node_gemm_kernel(const float* __restrict__ X, const float* __restrict__ Wl,
                      const float* __restrict__ bl, int zbase)
{
    extern __shared__ float sm[];
    float* As = sm;                  // [128][36] (m,k)
    float* Bs = sm + NAS_FLOATS;     // [32][132] (k,n)
    float* Cs = sm;                  // [128][132] aliases As/Bs

    int z = blockIdx.z + zbase;          // 0:A 1:B 2:D 3:E
    int widx = (z < 2) ? z : z + 1;      // W indices {0,1,3,4}
    const float* W    = Wl + widx * D * D;
    const float* bias = bl + widx * D;
    float* C;
    switch (z) { case 0: C = g_Ah; break; case 1: C = g_Bh; break;
                 case 2: C = g_Dh; break; default: C = g_Eh; break; }

    int tid = threadIdx.x;
    int warp = tid >> 5;
    int wm = warp >> 1;
    int wn = warp & 1;
    int row0 = blockIdx.x * 128;

    wmma::fragment<wmma::accumulator, 16, 16, 8, float> cfrag[2][4];
#pragma unroll
    for (int i = 0; i < 2; i++)
#pragma unroll
        for (int j = 0; j < 4; j++) wmma::fill_fragment(cfrag[i][j], 0.f);

    for (int kc = 0; kc < D; kc += 32) {
#pragma unroll
        for (int p = 0; p < 4; p++) {
            int s = tid + 256 * p;
            int m = s >> 3, c4 = (s & 7) << 2;
            int r = row0 + m;
            float4 v = (r < NN) ? *(const float4*)(X + (size_t)r * D + kc + c4)
                                : make_float4(0.f, 0.f, 0.f, 0.f);
            float* a = As + m * NAS_STRIDE + c4;
            a[0] = to_tf32(v.x); a[1] = to_tf32(v.y);
            a[2] = to_tf32(v.z); a[3] = to_tf32(v.w);
        }
#pragma unroll
        for (int p = 0; p < 4; p++) {
            int s = tid + 256 * p;
            int k = s >> 5, c4 = (s & 31) << 2;
            float4 v = *(const float4*)(W + (kc + k) * D + c4);
            float* bptr = Bs + k * NBS_STRIDE + c4;
            bptr[0] = to_tf32(v.x); bptr[1] = to_tf32(v.y);
            bptr[2] = to_tf32(v.z); bptr[3] = to_tf32(v.w);
        }
        __syncthreads();
#pragma unroll
        for (int ks = 0; ks < 4; ks++) {
            wmma::fragment<wmma::matrix_a, 16, 16, 8, wmma::precision::tf32, wmma::row_major> af[2];
            wmma::fragment<wmma::matrix_b, 16, 16, 8, wmma::precision::tf32, wmma::row_major> bf[4];
#pragma unroll
            for (int i = 0; i < 2; i++)
                wmma::load_matrix_sync(af[i], As + (wm * 32 + i * 16) * NAS_STRIDE + ks * 8, NAS_STRIDE);
#pragma unroll
            for (int j = 0; j < 4; j++)
                wmma::load_matrix_sync(bf[j], Bs + ks * 8 * NBS_STRIDE + wn * 64 + j * 16, NBS_STRIDE);
#pragma unroll
            for (int i = 0; i < 2; i++)
#pragma unroll
                for (int j = 0; j < 4; j++)
                    wmma::mma_sync(cfrag[i][j], af[i], bf[j], cfrag[i][j]);
        }
        __syncthreads();
    }

#pragma unroll
    for (int i = 0; i < 2; i++)
#pragma unroll
        for (int j = 0; j < 4; j++)
            wmma::store_matrix_sync(Cs + (wm * 32 + i * 16) * NCS_STRIDE + wn * 64 + j * 16,
                                    cfrag[i][j], NCS_STRIDE, wmma::mem_row_major);
    __syncthreads();

    int tx = tid & 15, ty = tid >> 4;
    float4 bi0 = *(const float4*)(bias + tx * 8);
    float4 bi1 = *(const float4*)(bias + tx * 8 + 4);
#pragma unroll
    for (int i = 0; i < 8; i++) {
        int rl = ty * 8 + i;
        int r  = row0 + rl;
        if (r >= NN) break;
        const float* crow = Cs + rl * NCS_STRIDE + tx * 8;
        float4 o0 = make_float4(crow[0] + bi0.x, crow[1] + bi0.y,
                                crow[2] + bi0.z, crow[3] + bi0.w);
        float4 o1 = make_float4(crow[4] + bi1.x, crow[5] + bi1.y,
                                crow[6] + bi1.z, crow[7] + bi1.w);
        *(float4*)(C + (size_t)r * D + tx * 8)     = o0;
        *(float4*)(C + (size_t)r * D + tx * 8 + 4) = o1;
    }
}

// ---------------- fused edge kernel (tf32 WMMA, BM=128) ----------------------
#define AS_STRIDE 36
#define BS_STRIDE 132
#define CS_STRIDE 132
#define AS_FLOATS (128 * AS_STRIDE)
#define BS_FLOATS (32 * BS_STRIDE)
#define CS_FLOATS (128 * CS_STRIDE)
#define AB_FLOATS (AS_FLOATS + BS_FLOATS)
#define EDGE_SMEM_FLOATS (AB_FLOATS > CS_FLOATS ? AB_FLOATS : CS_FLOATS)
#define EDGE_SMEM_BYTES (EDGE_SMEM_FLOATS * 4)

__global__ __launch_bounds__(256)
void edge_gemm_fused(const float* __restrict__ Xe, const float* __restrict__ W,
                     const float* __restrict__ bias,
                     const int* __restrict__ src, const int* __restrict__ dst,
                     int do_agg)
{
    extern __shared__ float sm[];
    float* As = sm;
    float* Bs = sm + AS_FLOATS;
    float* Cs = sm;                         // aliases As/Bs
    __shared__ float s_sum[D], s_sq[D];

    int tid = threadIdx.x;
    if (tid < D) { s_sum[tid] = 0.f; s_sq[tid] = 0.f; }
    int warp = tid >> 5;
    int wm = warp >> 1;
    int wn = warp & 1;
    int row0 = blockIdx.x * 128;

    wmma::fragment<wmma::accumulator, 16, 16, 8, float> cfrag[2][4];
#pragma unroll
    for (int i = 0; i < 2; i++)
#pragma unroll
        for (int j = 0; j < 4; j++) wmma::fill_fragment(cfrag[i][j], 0.f);

    for (int kc = 0; kc < D; kc += 32) {
#pragma unroll
        for (int p = 0; p < 4; p++) {
            int s = tid + 256 * p;
            int m = s >> 3, c4 = (s & 7) << 2;
            float4 v = *(const float4*)(Xe + (size_t)(row0 + m) * D + kc + c4);
            float* a = As + m * AS_STRIDE + c4;
            a[0] = to_tf32(v.x); a[1] = to_tf32(v.y);
            a[2] = to_tf32(v.z); a[3] = to_tf32(v.w);
        }
#pragma unroll
        for (int p = 0; p < 4; p++) {
            int s = tid + 256 * p;
            int k = s >> 5, c4 = (s & 31) << 2;
            float4 v = *(const float4*)(W + (kc + k) * D + c4);
            float* bptr = Bs + k * BS_STRIDE + c4;
            bptr[0] = to_tf32(v.x); bptr[1] = to_tf32(v.y);
            bptr[2] = to_tf32(v.z); bptr[3] = to_tf32(v.w);
        }
        __syncthreads();
#pragma unroll
        for (int ks = 0; ks < 4; ks++) {
            wmma::fragment<wmma::matrix_a, 16, 16, 8, wmma::precision::tf32, wmma::row_major> af[2];
            wmma::fragment<wmma::matrix_b, 16, 16, 8, wmma::precision::tf32, wmma::row_major> bf[4];
#pragma unroll
            for (int i = 0; i < 2; i++)
                wmma::load_matrix_sync(af[i], As + (wm * 32 + i * 16) * AS_STRIDE + ks * 8, AS_STRIDE);
#pragma unroll
            for (int j = 0; j < 4; j++)
                wmma::load_matrix_sync(bf[j], Bs + ks * 8 * BS_STRIDE + wn * 64 + j * 16, BS_STRIDE);
#pragma unroll
            for (int i = 0; i < 2; i++)
#pragma unroll
                for (int j = 0; j < 4; j++)
                    wmma::mma_sync(cfrag[i][j], af[i], bf[j], cfrag[i][j]);
        }
        __syncthreads();
    }

#pragma unroll
    for (int i = 0; i < 2; i++)
#pragma unroll
        for (int j = 0; j < 4; j++)
            wmma::store_matrix_sync(Cs + (wm * 32 + i * 16) * CS_STRIDE + wn * 64 + j * 16,
                                    cfrag[i][j], CS_STRIDE, wmma::mem_row_major);
    __syncthreads();

    int tx = tid & 15, ty = tid >> 4;
    float4 bi0 = *(const float4*)(bias + tx * 8);
    float4 bi1 = *(const float4*)(bias + tx * 8 + 4);
    float lsum[8], lsq[8];
#pragma unroll
    for (int j = 0; j < 8; j++) { lsum[j] = 0.f; lsq[j] = 0.f; }

#pragma unroll
    for (int i = 0; i < 8; i++) {
        int rl = ty * 8 + i;
        int r  = row0 + rl;
        const float* crow = Cs + rl * CS_STRIDE + tx * 8;
        int sN = src[r], dN = dst[r];
        const float4* dh = (const float4*)(g_Dh + (size_t)sN * D + tx * 8);
        const float4* eh = (const float4*)(g_Eh + (size_t)dN * D + tx * 8);
        float4 d0 = dh[0], d1 = dh[1];
        float4 e0 = eh[0], e1 = eh[1];
        float v[8];
        v[0] = crow[0] + bi0.x + d0.x + e0.x;
        v[1] = crow[1] + bi0.y + d0.y + e0.y;
        v[2] = crow[2] + bi0.z + d0.z + e0.z;
        v[3] = crow[3] + bi0.w + d0.w + e0.w;
        v[4] = crow[4] + bi1.x + d1.x + e1.x;
        v[5] = crow[5] + bi1.y + d1.y + e1.y;
        v[6] = crow[6] + bi1.z + d1.z + e1.z;
        v[7] = crow[7] + bi1.w + d1.w + e1.w;
        *(float4*)(g_etmp + (size_t)r * D + tx * 8)     = make_float4(v[0], v[1], v[2], v[3]);
        *(float4*)(g_etmp + (size_t)r * D + tx * 8 + 4) = make_float4(v[4], v[5], v[6], v[7]);
#pragma unroll
        for (int j = 0; j < 8; j++) { lsum[j] += v[j]; lsq[j] += v[j] * v[j]; }
        if (do_agg) {
            const float4* bh = (const float4*)(g_Bh + (size_t)sN * D + tx * 8);
            float4 b0v = bh[0], b1v = bh[1];
            float bb[8] = {b0v.x, b0v.y, b0v.z, b0v.w, b1v.x, b1v.y, b1v.z, b1v.w};
            float sig[8];
#pragma unroll
            for (int j = 0; j < 8; j++) sig[j] = 1.f / (1.f + __expf(-v[j]));
            float* np = g_num + (size_t)dN * D + tx * 8;
            float* dp = g_den + (size_t)dN * D + tx * 8;
            red_add_v4(np,     sig[0] * bb[0], sig[1] * bb[1], sig[2] * bb[2], sig[3] * bb[3]);
            red_add_v4(np + 4, sig[4] * bb[4], sig[5] * bb[5], sig[6] * bb[6], sig[7] * bb[7]);
            red_add_v4(dp,     sig[0], sig[1], sig[2], sig[3]);
            red_add_v4(dp + 4, sig[4], sig[5], sig[6], sig[7]);
        }
    }

#pragma unroll
    for (int j = 0; j < 8; j++) {
        atomicAdd(&s_sum[tx * 8 + j], lsum[j]);
        atomicAdd(&s_sq[tx * 8 + j],  lsq[j]);
    }
    __syncthreads();
    if (tid < D) {
        atomicAdd(&g_stats[2 * D + tid], s_sum[tid]);
        atomicAdd(&g_stats[3 * D + tid], s_sq[tid]);
    }
}

// ---------------- h_pre = Ah + num/(den+eps), + BN stats (float4) ------------
// 256 threads: tx = lane-in-32 covers 128 cols as float4; ty = 8 rows in flight.
__global__ __launch_bounds__(256)
void hpre_kernel()
{
    __shared__ float s_sum[D], s_sq[D];
    int tid = threadIdx.x;
    if (tid < D) { s_sum[tid] = 0.f; s_sq[tid] = 0.f; }
    __syncthreads();

    int tx = tid & 31;          // col group: cols tx*4 .. tx*4+3
    int ty = tid >> 5;          // 0..7
    int row0 = blockIdx.x * 64;
    int c4 = tx << 2;

    float ls0 = 0.f, ls1 = 0.f, ls2 = 0.f, ls3 = 0.f;
    float lq0 = 0.f, lq1 = 0.f, lq2 = 0.f, lq3 = 0.f;
    for (int r = row0 + ty; r < row0 + 64; r += 8) {
        size_t idx = (size_t)r * D + c4;
        float4 a = *(const float4*)(g_Ah + idx);
        float4 n = *(const float4*)(g_num + idx);
        float4 d = *(const float4*)(g_den + idx);
        float4 v;
        v.x = a.x + n.x / (d.x + 1e-6f);
        v.y = a.y + n.y / (d.y + 1e-6f);
        v.z = a.z + n.z / (d.z + 1e-6f);
        v.w = a.w + n.w / (d.w + 1e-6f);
        *(float4*)(g_hpre + idx) = v;
        ls0 += v.x; ls1 += v.y; ls2 += v.z; ls3 += v.w;
        lq0 += v.x * v.x; lq1 += v.y * v.y; lq2 += v.z * v.z; lq3 += v.w * v.w;
    }
    atomicAdd(&s_sum[c4 + 0], ls0); atomicAdd(&s_sum[c4 + 1], ls1);
    atomicAdd(&s_sum[c4 + 2], ls2); atomicAdd(&s_sum[c4 + 3], ls3);
    atomicAdd(&s_sq[c4 + 0], lq0);  atomicAdd(&s_sq[c4 + 1], lq1);
    atomicAdd(&s_sq[c4 + 2], lq2);  atomicAdd(&s_sq[c4 + 3], lq3);
    __syncthreads();
    if (tid < D) {
        atomicAdd(&g_stats[tid],     s_sum[tid]);
        atomicAdd(&g_stats[D + tid], s_sq[tid]);
    }
}

// ---------------- finalize BN statistics -------------------------------------
__global__ void finalize_stats_kernel()
{
    int c = threadIdx.x;
    float inN = 1.f / (float)NN, inE = 1.f / (float)NE;
    float hmu  = g_stats[c] * inN;
    float hvar = g_stats[D + c] * inN - hmu * hmu;
    g_bn[c]     = hmu;
    g_bn[D + c] = rsqrtf(fmaxf(hvar, 0.f) + 1e-5f);
    float emu  = g_stats[2 * D + c] * inE;
    float evar = g_stats[3 * D + c] * inE - emu * emu;
    g_bn[2 * D + c] = emu;
    g_bn[3 * D + c] = rsqrtf(fmaxf(evar, 0.f) + 1e-5f);
}

// ---------------- h = h_in + relu(bn(h_pre)) ---------------------------------
__global__ __launch_bounds__(256)
void h_apply_kernel(const float* __restrict__ hin, float* __restrict__ hout,
                    const float* __restrict__ gamma, const float* __restrict__ beta)
{
    int i = blockIdx.x * blockDim.x + threadIdx.x;
    if (i >= NN * D / 4) return;
    int c = (i & 31) << 2;
    float4 p  = ((const float4*)g_hpre)[i];
    float4 x  = ((const float4*)hin)[i];
    float4 mu = *(const float4*)(g_bn + c);
    float4 rs = *(const float4*)(g_bn + D + c);
    float4 ga = *(const float4*)(gamma + c);
    float4 be = *(const float4*)(beta + c);
    float4 o;
    o.x = x.x + fmaxf((p.x - mu.x) * rs.x * ga.x + be.x, 0.f);
    o.y = x.y + fmaxf((p.y - mu.y) * rs.y * ga.y + be.y, 0.f);
    o.z = x.z + fmaxf((p.z - mu.z) * rs.z * ga.z + be.z, 0.f);
    o.w = x.w + fmaxf((p.w - mu.w) * rs.w * ga.w + be.w, 0.f);
    ((float4*)hout)[i] = o;
}

// ---------------- e = e_in + relu(bn(e_tmp)) ----------------------------------
__global__ __launch_bounds__(256)
void e_apply_kernel(const float* __restrict__ ein, float* __restrict__ eout,
                    const float* __restrict__ gamma, const float* __restrict__ beta)
{
    int i = blockIdx.x * blockDim.x + threadIdx.x;
    if (i >= NE * D / 4) return;
    int c = (i & 31) << 2;
    float4 p  = ((const float4*)g_etmp)[i];
    float4 x  = ((const float4*)ein)[i];
    float4 mu = *(const float4*)(g_bn + 2 * D + c);
    float4 rs = *(const float4*)(g_bn + 3 * D + c);
    float4 ga = *(const float4*)(gamma + c);
    float4 be = *(const float4*)(beta + c);
    float4 o;
    o.x = x.x + fmaxf((p.x - mu.x) * rs.x * ga.x + be.x, 0.f);
    o.y = x.y + fmaxf((p.y - mu.y) * rs.y * ga.y + be.y, 0.f);
    o.z = x.z + fmaxf((p.z - mu.z) * rs.z * ga.z + be.z, 0.f);
    o.w = x.w + fmaxf((p.w - mu.w) * rs.w * ga.w + be.w, 0.f);
    ((float4*)eout)[i] = o;
}

// ---------------- launcher ----------------------------------------------------
extern "C" void kernel_launch(void* const* d_in, const int* in_sizes, int n_in,
                              void* d_out, int out_size)
{
    const float* h_in  = (const float*)d_in[0];
    const float* e_in  = (const float*)d_in[1];
    const float* W     = (const float*)d_in[2];
    const float* b     = (const float*)d_in[3];
    const float* gamma = (const float*)d_in[4];
    const float* beta  = (const float*)d_in[5];
    const int*   src   = (const int*)d_in[6];
    const int*   dst   = (const int*)d_in[7];
    float* out = (float*)d_out;

    static int init_done = 0;
    static cudaStream_t s1;
    static cudaEvent_t evFork[NL], evJoin[NL];
    if (!init_done) {
        cudaFuncSetAttribute(edge_gemm_fused,
                             cudaFuncAttributeMaxDynamicSharedMemorySize, EDGE_SMEM_BYTES);
        cudaFuncSetAttribute(node_gemm_kernel,
                             cudaFuncAttributeMaxDynamicSharedMemorySize, NODE_SMEM_BYTES);
        cudaStreamCreateWithFlags(&s1, cudaStreamNonBlocking);
        for (int i = 0; i < NL; i++) {
            cudaEventCreateWithFlags(&evFork[i], cudaEventDisableTiming);
            cudaEventCreateWithFlags(&evJoin[i], cudaEventDisableTiming);
        }
        init_done = 1;
    }

    float *p_num, *p_den, *p_stats, *p_h, *p_e;
    cudaGetSymbolAddress((void**)&p_num,   g_num);
    cudaGetSymbolAddress((void**)&p_den,   g_den);
    cudaGetSymbolAddress((void**)&p_stats, g_stats);
    cudaGetSymbolAddress((void**)&p_h,     g_h);
    cudaGetSymbolAddress((void**)&p_e,     g_e);

    // Output h = h_before (the input h, unchanged by reference semantics)
    cudaMemcpyAsync(out, h_in, (size_t)NN * D * sizeof(float),
                    cudaMemcpyDeviceToDevice, 0);

    for (int l = 0; l < NL; l++) {
        const float* hcur = (l == 0) ? h_in : p_h;
        const float* ecur = (l == 0) ? e_in : p_e;
        const float* Wl = W + (size_t)l * 5 * D * D;
        const float* bl = b + (size_t)l * 5 * D;
        int last = (l == NL - 1);

        cudaMemsetAsync(p_stats, 0, 4 * D * sizeof(float), 0);
        if (!last) {
            cudaMemsetAsync(p_num, 0, (size_t)NN * D * sizeof(float), 0);
            cudaMemsetAsync(p_den, 0, (size_t)NN * D * sizeof(float), 0);
        }

        if (!last)
            node_gemm_kernel<<<dim3(NODE_GRID, 1, 4), 256, NODE_SMEM_BYTES>>>(hcur, Wl, bl, 0);
        else
            node_gemm_kernel<<<dim3(NODE_GRID, 1, 2), 256, NODE_SMEM_BYTES>>>(hcur, Wl, bl, 2);

        // join: previous layer's e_apply (on s1) must have produced p_e
        if (l > 0)
            cudaStreamWaitEvent(0, evJoin[l - 1], 0);

        edge_gemm_fused<<<NE / 128, 256, EDGE_SMEM_BYTES>>>(
            ecur, Wl + 2 * D * D, bl + 2 * D, src, dst, last ? 0 : 1);

        if (!last) hpre_kernel<<<NN / 64, 256>>>();
        finalize_stats_kernel<<<1, D>>>();

        if (!last) {
            // fork: e_apply on s1 overlaps h_apply + next layer's node GEMM
            cudaEventRecord(evFork[l], 0);
            cudaStreamWaitEvent(s1, evFork[l], 0);
            e_apply_kernel<<<(NE * D / 4 + 255) / 256, 256, 0, s1>>>(
                ecur, p_e, gamma + (size_t)(l * 2 + 1) * D, beta + (size_t)(l * 2 + 1) * D);
            cudaEventRecord(evJoin[l], s1);

            h_apply_kernel<<<(NN * D / 4 + 255) / 256, 256>>>(
                hcur, p_h, gamma + (size_t)(l * 2) * D, beta + (size_t)(l * 2) * D);
        } else {
            e_apply_kernel<<<(NE * D / 4 + 255) / 256, 256>>>(
                ecur, out + (size_t)NN * D,
                gamma + (size_t)(l * 2 + 1) * D, beta + (size_t)(l * 2 + 1) * D);
        }
    }
}